// round 9
// baseline (speedup 1.0000x reference)
#include <cuda_runtime.h>

// Problem constants (N=100000, E=1600000, ND=ED=OD=32)
#define NODES_MAX 100000
#define EDGES_MAX 1600000
#define SCAN_T 1024

// Device-global scratch (no allocations allowed).
__device__ int g_count[NODES_MAX];     // in-degree histogram
__device__ int g_rowtmp[NODES_MAX];    // block-local exclusive scan
__device__ int g_row[NODES_MAX];       // CSR row offsets
__device__ int g_cursor[NODES_MAX];    // permutation cursors
__device__ int g_part[256];            // per-block scan partials
__device__ int g_esrc[EDGES_MAX];      // sorted-by-dst: src node id
__device__ int g_eeid[EDGES_MAX];      // sorted-by-dst: original edge id

// ---------------------------------------------------------------------------
// 1. zero histogram
// ---------------------------------------------------------------------------
__global__ void mp_zero_kernel(int n_nodes) {
    int i = blockIdx.x * blockDim.x + threadIdx.x;
    if (i < n_nodes) g_count[i] = 0;
}

// ---------------------------------------------------------------------------
// 2. in-degree histogram (RED.ADD, result unused)
// ---------------------------------------------------------------------------
__global__ void mp_hist_kernel(const int* __restrict__ dst, int n_edges) {
    int e = blockIdx.x * blockDim.x + threadIdx.x;
    if (e < n_edges) atomicAdd(&g_count[__ldg(dst + e)], 1);
}

// ---------------------------------------------------------------------------
// 3a. block-wise exclusive scan of g_count -> g_rowtmp, block sums -> g_part
// ---------------------------------------------------------------------------
__global__ void mp_scan1_kernel(int n_nodes) {
    __shared__ int sh[SCAN_T];
    int t = threadIdx.x, b = blockIdx.x;
    int idx = b * SCAN_T + t;
    int v = (idx < n_nodes) ? g_count[idx] : 0;
    sh[t] = v;
    __syncthreads();
    for (int off = 1; off < SCAN_T; off <<= 1) {
        int x = 0;
        if (t >= off) x = sh[t - off];
        __syncthreads();
        if (t >= off) sh[t] += x;
        __syncthreads();
    }
    if (idx < n_nodes) g_rowtmp[idx] = sh[t] - v;   // exclusive
    if (t == SCAN_T - 1) g_part[b] = sh[t];          // block total
}

// 3b. exclusive scan of g_part (single block; nb <= SCAN_T)
__global__ void mp_scan2_kernel(int nb) {
    __shared__ int sh[SCAN_T];
    int t = threadIdx.x;
    int v = (t < nb) ? g_part[t] : 0;
    sh[t] = v;
    __syncthreads();
    for (int off = 1; off < SCAN_T; off <<= 1) {
        int x = 0;
        if (t >= off) x = sh[t - off];
        __syncthreads();
        if (t >= off) sh[t] += x;
        __syncthreads();
    }
    if (t < nb) g_part[t] = sh[t] - v;
}

// 3c. combine -> g_row, and init cursors
__global__ void mp_scan3_kernel(int n_nodes) {
    int idx = blockIdx.x * blockDim.x + threadIdx.x;
    if (idx < n_nodes) {
        int r = g_rowtmp[idx] + g_part[blockIdx.x * blockDim.x / SCAN_T == 0
                                           ? idx / SCAN_T : idx / SCAN_T];
        g_row[idx] = r;
        g_cursor[idx] = r;
    }
}

// ---------------------------------------------------------------------------
// 4. permutation: scatter (src, eid) into dst-sorted order. Only int atomics.
// ---------------------------------------------------------------------------
__global__ void mp_permute_kernel(const int* __restrict__ src,
                                  const int* __restrict__ dst,
                                  int n_edges) {
    int e = blockIdx.x * blockDim.x + threadIdx.x;
    if (e >= n_edges) return;
    int d = __ldg(dst + e);
    int pos = atomicAdd(&g_cursor[d], 1);
    g_esrc[pos] = __ldg(src + e);
    g_eeid[pos] = e;
}

// ---------------------------------------------------------------------------
// 5. fused gather + epilogue. Warp per node:
//    s0 = sum node_x[src[e]],  s1 = sum edge_x[e]   over in-edges (CSR walk)
//    agg = [s0,s1] @ W_pre + deg*b_pre ; z = deg>0 ? relu(agg) : z_init
//    h   = relu([node_x, z] @ W_upd + b_upd)
// ---------------------------------------------------------------------------
__global__ void __launch_bounds__(256)
mp_gather_kernel(const float* __restrict__ node_x,
                 const float* __restrict__ edge_x,
                 const float* __restrict__ z_init,
                 const float* __restrict__ W_pre,   // [64,64]
                 const float* __restrict__ b_pre,   // [64]
                 const float* __restrict__ W_upd,   // [96,32]
                 const float* __restrict__ b_upd,   // [32]
                 float* __restrict__ out,           // [N,32]
                 int n_nodes) {
    __shared__ float sWp[64 * 64];
    __shared__ float sWu[96 * 32];
    __shared__ float sbp[64];
    __shared__ float sbu[32];

    for (int k = threadIdx.x; k < 64 * 64; k += blockDim.x) sWp[k] = W_pre[k];
    for (int k = threadIdx.x; k < 96 * 32; k += blockDim.x) sWu[k] = W_upd[k];
    if (threadIdx.x < 64) sbp[threadIdx.x] = b_pre[threadIdx.x];
    if (threadIdx.x < 32) sbu[threadIdx.x] = b_upd[threadIdx.x];
    __syncthreads();

    int n = (blockIdx.x * blockDim.x + threadIdx.x) >> 5;   // warp = node
    if (n >= n_nodes) return;                               // uniform per warp
    int lane = threadIdx.x & 31;

    int start = g_row[n];
    int deg   = g_count[n];

    float s0 = 0.f, s1 = 0.f;
    for (int base = 0; base < deg; base += 32) {
        int m = deg - base;
        if (m > 32) m = 32;
        int sidx = 0, eidx = 0;
        if (lane < m) {
            sidx = g_esrc[start + base + lane];
            eidx = g_eeid[start + base + lane];
        }
        int j = 0;
        for (; j + 4 <= m; j += 4) {   // 4-wide unroll for MLP
            int s_0 = __shfl_sync(0xffffffffu, sidx, j);
            int e_0 = __shfl_sync(0xffffffffu, eidx, j);
            int s_1 = __shfl_sync(0xffffffffu, sidx, j + 1);
            int e_1 = __shfl_sync(0xffffffffu, eidx, j + 1);
            int s_2 = __shfl_sync(0xffffffffu, sidx, j + 2);
            int e_2 = __shfl_sync(0xffffffffu, eidx, j + 2);
            int s_3 = __shfl_sync(0xffffffffu, sidx, j + 3);
            int e_3 = __shfl_sync(0xffffffffu, eidx, j + 3);
            float n0 = __ldg(node_x + (size_t)s_0 * 32 + lane);
            float x0 = __ldg(edge_x + (size_t)e_0 * 32 + lane);
            float n1 = __ldg(node_x + (size_t)s_1 * 32 + lane);
            float x1 = __ldg(edge_x + (size_t)e_1 * 32 + lane);
            float n2 = __ldg(node_x + (size_t)s_2 * 32 + lane);
            float x2 = __ldg(edge_x + (size_t)e_2 * 32 + lane);
            float n3 = __ldg(node_x + (size_t)s_3 * 32 + lane);
            float x3 = __ldg(edge_x + (size_t)e_3 * 32 + lane);
            s0 += (n0 + n1) + (n2 + n3);
            s1 += (x0 + x1) + (x2 + x3);
        }
        for (; j < m; j++) {
            int s_0 = __shfl_sync(0xffffffffu, sidx, j);
            int e_0 = __shfl_sync(0xffffffffu, eidx, j);
            s0 += __ldg(node_x + (size_t)s_0 * 32 + lane);
            s1 += __ldg(edge_x + (size_t)e_0 * 32 + lane);
        }
    }

    float dg = (float)deg;

    // agg = [s0,s1] @ W_pre + deg * b_pre  (lane j owns outputs j, j+32)
    float a0 = dg * sbp[lane];
    float a1 = dg * sbp[32 + lane];
#pragma unroll
    for (int i = 0; i < 32; i++) {
        float si = __shfl_sync(0xffffffffu, s0, i);
        a0 = fmaf(si, sWp[i * 64 + lane], a0);
        a1 = fmaf(si, sWp[i * 64 + 32 + lane], a1);
    }
#pragma unroll
    for (int i = 0; i < 32; i++) {
        float si = __shfl_sync(0xffffffffu, s1, i);
        a0 = fmaf(si, sWp[(32 + i) * 64 + lane], a0);
        a1 = fmaf(si, sWp[(32 + i) * 64 + 32 + lane], a1);
    }

    float z0, z1;
    if (deg > 0) {
        z0 = fmaxf(a0, 0.f);
        z1 = fmaxf(a1, 0.f);
    } else {
        z0 = z_init[(size_t)n * 64 + lane];
        z1 = z_init[(size_t)n * 64 + 32 + lane];
    }

    // h = relu([node_x, z] @ W_upd + b_upd)
    float x = node_x[(size_t)n * 32 + lane];
    float h = sbu[lane];
#pragma unroll
    for (int i = 0; i < 32; i++)
        h = fmaf(__shfl_sync(0xffffffffu, x, i), sWu[i * 32 + lane], h);
#pragma unroll
    for (int i = 0; i < 32; i++)
        h = fmaf(__shfl_sync(0xffffffffu, z0, i), sWu[(32 + i) * 32 + lane], h);
#pragma unroll
    for (int i = 0; i < 32; i++)
        h = fmaf(__shfl_sync(0xffffffffu, z1, i), sWu[(64 + i) * 32 + lane], h);

    out[(size_t)n * 32 + lane] = fmaxf(h, 0.f);
}

// ---------------------------------------------------------------------------
// Launch. Inputs: node_x, edge_x, z_init, W_pre, b_pre, W_upd, b_upd, src, dst
// ---------------------------------------------------------------------------
extern "C" void kernel_launch(void* const* d_in, const int* in_sizes, int n_in,
                              void* d_out, int out_size) {
    const float* node_x = (const float*)d_in[0];
    const float* edge_x = (const float*)d_in[1];
    const float* z_init = (const float*)d_in[2];
    const float* W_pre  = (const float*)d_in[3];
    const float* b_pre  = (const float*)d_in[4];
    const float* W_upd  = (const float*)d_in[5];
    const float* b_upd  = (const float*)d_in[6];
    const int*   src    = (const int*)d_in[7];
    const int*   dst    = (const int*)d_in[8];
    float* out = (float*)d_out;

    int n_nodes = in_sizes[0] / 32;   // 100000
    int n_edges = in_sizes[7];        // 1600000
    int nb = (n_nodes + SCAN_T - 1) / SCAN_T;   // 98 scan blocks

    mp_zero_kernel<<<(n_nodes + 255) / 256, 256>>>(n_nodes);
    mp_hist_kernel<<<(n_edges + 255) / 256, 256>>>(dst, n_edges);
    mp_scan1_kernel<<<nb, SCAN_T>>>(n_nodes);
    mp_scan2_kernel<<<1, SCAN_T>>>(nb);
    mp_scan3_kernel<<<nb, SCAN_T>>>(n_nodes);
    mp_permute_kernel<<<(n_edges + 255) / 256, 256>>>(src, dst, n_edges);
    mp_gather_kernel<<<(n_nodes * 32 + 255) / 256, 256>>>(
        node_x, edge_x, z_init, W_pre, b_pre, W_upd, b_upd, out, n_nodes);
}

// round 10
// speedup vs baseline: 1.8616x; 1.8616x over previous
#include <cuda_runtime.h>

// Problem constants (N=100000, E=1600000, ND=ED=OD=32)
#define NODES_MAX 100000
#define EDGES_MAX 1600000
#define SCAN_T 1024

// Device-global scratch (no allocations allowed).
__device__ int   g_count[NODES_MAX];      // in-degree
__device__ int   g_rowtmp[NODES_MAX];     // block-local exclusive scan
__device__ int   g_row[NODES_MAX];        // CSR row offsets
__device__ int   g_cursor[NODES_MAX];     // permutation cursors
__device__ int   g_part[256];             // scan partials
__device__ int2  g_epair[EDGES_MAX];      // dst-sorted (src, eid)
__device__ float g_S[NODES_MAX * 64];     // per-node [sum node_x | sum edge_x]

// ---------------------------------------------------------------------------
// 1. zero histogram
// ---------------------------------------------------------------------------
__global__ void mp_zero_kernel(int n_nodes) {
    int i = blockIdx.x * blockDim.x + threadIdx.x;
    if (i < n_nodes) g_count[i] = 0;
}

// ---------------------------------------------------------------------------
// 2. in-degree histogram
// ---------------------------------------------------------------------------
__global__ void mp_hist_kernel(const int* __restrict__ dst, int n_edges) {
    int e = blockIdx.x * blockDim.x + threadIdx.x;
    if (e < n_edges) atomicAdd(&g_count[__ldg(dst + e)], 1);
}

// ---------------------------------------------------------------------------
// 3a/3b/3c. exclusive scan of g_count -> g_row (+ init cursors)
// ---------------------------------------------------------------------------
__global__ void mp_scan1_kernel(int n_nodes) {
    __shared__ int sh[SCAN_T];
    int t = threadIdx.x, b = blockIdx.x;
    int idx = b * SCAN_T + t;
    int v = (idx < n_nodes) ? g_count[idx] : 0;
    sh[t] = v;
    __syncthreads();
    for (int off = 1; off < SCAN_T; off <<= 1) {
        int x = 0;
        if (t >= off) x = sh[t - off];
        __syncthreads();
        if (t >= off) sh[t] += x;
        __syncthreads();
    }
    if (idx < n_nodes) g_rowtmp[idx] = sh[t] - v;
    if (t == SCAN_T - 1) g_part[b] = sh[t];
}

__global__ void mp_scan2_kernel(int nb) {
    __shared__ int sh[SCAN_T];
    int t = threadIdx.x;
    int v = (t < nb) ? g_part[t] : 0;
    sh[t] = v;
    __syncthreads();
    for (int off = 1; off < SCAN_T; off <<= 1) {
        int x = 0;
        if (t >= off) x = sh[t - off];
        __syncthreads();
        if (t >= off) sh[t] += x;
        __syncthreads();
    }
    if (t < nb) g_part[t] = sh[t] - v;
}

__global__ void mp_scan3_kernel(int n_nodes) {
    int idx = blockIdx.x * blockDim.x + threadIdx.x;
    if (idx < n_nodes) {
        int r = g_rowtmp[idx] + g_part[idx / SCAN_T];
        g_row[idx] = r;
        g_cursor[idx] = r;
    }
}

// ---------------------------------------------------------------------------
// 4. permutation: (src, eid) into dst-sorted order (int atomics only)
// ---------------------------------------------------------------------------
__global__ void mp_permute_kernel(const int* __restrict__ src,
                                  const int* __restrict__ dst,
                                  int n_edges) {
    int e = blockIdx.x * blockDim.x + threadIdx.x;
    if (e >= n_edges) return;
    int d = __ldg(dst + e);
    int pos = atomicAdd(&g_cursor[d], 1);
    g_epair[pos] = make_int2(__ldg(src + e), e);
}

// ---------------------------------------------------------------------------
// 5. gather: warp per node, CSR walk. Writes S[n] = [sum node_x | sum edge_x].
//    No epilogue here (moved to a tiled GEMM kernel).
// ---------------------------------------------------------------------------
__global__ void __launch_bounds__(256)
mp_gather_kernel(const float* __restrict__ node_x,
                 const float* __restrict__ edge_x,
                 int n_nodes) {
    int n = (blockIdx.x * blockDim.x + threadIdx.x) >> 5;
    if (n >= n_nodes) return;
    int lane = threadIdx.x & 31;

    int start = g_row[n];
    int deg   = g_count[n];

    float s0 = 0.f, s1 = 0.f;
    for (int base = 0; base < deg; base += 32) {
        int m = deg - base;
        if (m > 32) m = 32;
        int2 p = make_int2(0, 0);
        if (lane < m) p = g_epair[start + base + lane];
        int j = 0;
        for (; j + 4 <= m; j += 4) {      // keep 8 loads in flight
            int s_0 = __shfl_sync(0xffffffffu, p.x, j);
            int e_0 = __shfl_sync(0xffffffffu, p.y, j);
            int s_1 = __shfl_sync(0xffffffffu, p.x, j + 1);
            int e_1 = __shfl_sync(0xffffffffu, p.y, j + 1);
            int s_2 = __shfl_sync(0xffffffffu, p.x, j + 2);
            int e_2 = __shfl_sync(0xffffffffu, p.y, j + 2);
            int s_3 = __shfl_sync(0xffffffffu, p.x, j + 3);
            int e_3 = __shfl_sync(0xffffffffu, p.y, j + 3);
            float n0 = __ldg(node_x + (size_t)s_0 * 32 + lane);
            float x0 = __ldg(edge_x + (size_t)e_0 * 32 + lane);
            float n1 = __ldg(node_x + (size_t)s_1 * 32 + lane);
            float x1 = __ldg(edge_x + (size_t)e_1 * 32 + lane);
            float n2 = __ldg(node_x + (size_t)s_2 * 32 + lane);
            float x2 = __ldg(edge_x + (size_t)e_2 * 32 + lane);
            float n3 = __ldg(node_x + (size_t)s_3 * 32 + lane);
            float x3 = __ldg(edge_x + (size_t)e_3 * 32 + lane);
            s0 += (n0 + n1) + (n2 + n3);
            s1 += (x0 + x1) + (x2 + x3);
        }
        for (; j < m; j++) {
            int s_0 = __shfl_sync(0xffffffffu, p.x, j);
            int e_0 = __shfl_sync(0xffffffffu, p.y, j);
            s0 += __ldg(node_x + (size_t)s_0 * 32 + lane);
            s1 += __ldg(edge_x + (size_t)e_0 * 32 + lane);
        }
    }
    g_S[(size_t)n * 64 + lane]      = s0;
    g_S[(size_t)n * 64 + 32 + lane] = s1;
}

// ---------------------------------------------------------------------------
// 6. tiled epilogue GEMM, 64-node tiles, 256 threads.
//    Z = relu(S @ W_pre + deg*b_pre)  (deg==0 rows -> z_init)
//    H = relu([X | Z] @ W_upd + b_upd)
//    Buffer reuse keeps static smem < 48KB:
//      sA: holds S, then Z.   sW: holds W_pre, then W_upd.
// ---------------------------------------------------------------------------
__global__ void __launch_bounds__(256)
mp_epilogue_kernel(const float* __restrict__ node_x,
                   const float* __restrict__ z_init,
                   const float* __restrict__ W_pre,   // [64,64]
                   const float* __restrict__ b_pre,   // [64]
                   const float* __restrict__ W_upd,   // [96,32]
                   const float* __restrict__ b_upd,   // [32]
                   float* __restrict__ out,           // [N,32]
                   int n_nodes) {
    __shared__ float sA[64 * 65];     // S tile (pitch 65), later Z tile
    __shared__ float sW[64 * 64];     // W_pre [k][c], later W_upd [k*32+c]
    __shared__ float sX[64 * 33];     // node_x tile (pitch 33)
    __shared__ float sbp[64];
    __shared__ float sbu[32];
    __shared__ float sdeg[64];

    int t = threadIdx.x;
    int nb = blockIdx.x * 64;
    int nvalid = n_nodes - nb;
    if (nvalid > 64) nvalid = 64;

    // ---- stage tiles ----
    for (int idx = t; idx < 64 * 64; idx += 256) sW[idx] = W_pre[idx];
    for (int idx = t; idx < 64 * 64; idx += 256) {
        int r = idx >> 6, c = idx & 63;
        sA[r * 65 + c] = (r < nvalid) ? g_S[(size_t)(nb + r) * 64 + c] : 0.f;
    }
    for (int idx = t; idx < 64 * 32; idx += 256) {
        int r = idx >> 5, c = idx & 31;
        sX[r * 33 + c] = (r < nvalid) ? node_x[(size_t)(nb + r) * 32 + c] : 0.f;
    }
    if (t < 64) {
        sbp[t]  = b_pre[t];
        sdeg[t] = (t < nvalid) ? (float)g_count[nb + t] : 0.f;
    }
    if (t < 32) sbu[t] = b_upd[t];
    __syncthreads();

    // ---- GEMM1: 64x64 output, 4x4 micro-tile per thread ----
    float acc[4][4];
    {
        int tx = t & 15, ty = t >> 4;
        int c0 = tx * 4, r0 = ty * 4;
#pragma unroll
        for (int r = 0; r < 4; r++)
#pragma unroll
            for (int c = 0; c < 4; c++) acc[r][c] = sdeg[r0 + r] * sbp[c0 + c];

#pragma unroll 8
        for (int k = 0; k < 64; k++) {
            float a0 = sA[(r0 + 0) * 65 + k];
            float a1 = sA[(r0 + 1) * 65 + k];
            float a2 = sA[(r0 + 2) * 65 + k];
            float a3 = sA[(r0 + 3) * 65 + k];
            float4 bv = *(const float4*)&sW[k * 64 + c0];
#pragma unroll
            for (int c = 0; c < 4; c++) {
                float b = (c == 0) ? bv.x : (c == 1) ? bv.y : (c == 2) ? bv.z : bv.w;
                acc[0][c] = fmaf(a0, b, acc[0][c]);
                acc[1][c] = fmaf(a1, b, acc[1][c]);
                acc[2][c] = fmaf(a2, b, acc[2][c]);
                acc[3][c] = fmaf(a3, b, acc[3][c]);
            }
        }
    }
    __syncthreads();     // all reads of sA (S) and sW (W_pre) done

    // ---- write Z into sA; reload sW with W_upd ----
    {
        int tx = t & 15, ty = t >> 4;
        int c0 = tx * 4, r0 = ty * 4;
#pragma unroll
        for (int r = 0; r < 4; r++)
#pragma unroll
            for (int c = 0; c < 4; c++)
                sA[(r0 + r) * 65 + c0 + c] = fmaxf(acc[r][c], 0.f);
    }
    for (int idx = t; idx < 96 * 32; idx += 256) sW[idx] = W_upd[idx];
    __syncthreads();

    // ---- deg==0 rows take z_init (rare; correctness only) ----
    if (t < nvalid && sdeg[t] == 0.f) {
        for (int c = 0; c < 64; c++)
            sA[t * 65 + c] = z_init[(size_t)(nb + t) * 64 + c];
    }
    __syncthreads();

    // ---- GEMM2: 64x32 output, 2x4 micro-tile per thread ----
    {
        int tx = t & 7, ty = t >> 3;
        int c0 = tx * 4, r0 = ty * 2;
        float h[2][4];
#pragma unroll
        for (int r = 0; r < 2; r++)
#pragma unroll
            for (int c = 0; c < 4; c++) h[r][c] = sbu[c0 + c];

#pragma unroll 8
        for (int k = 0; k < 32; k++) {       // node_x part: rows 0..31 of W_upd
            float a0 = sX[(r0 + 0) * 33 + k];
            float a1 = sX[(r0 + 1) * 33 + k];
            float4 bv = *(const float4*)&sW[k * 32 + c0];
#pragma unroll
            for (int c = 0; c < 4; c++) {
                float b = (c == 0) ? bv.x : (c == 1) ? bv.y : (c == 2) ? bv.z : bv.w;
                h[0][c] = fmaf(a0, b, h[0][c]);
                h[1][c] = fmaf(a1, b, h[1][c]);
            }
        }
#pragma unroll 8
        for (int k = 0; k < 64; k++) {       // z part: rows 32..95 of W_upd
            float a0 = sA[(r0 + 0) * 65 + k];
            float a1 = sA[(r0 + 1) * 65 + k];
            float4 bv = *(const float4*)&sW[(32 + k) * 32 + c0];
#pragma unroll
            for (int c = 0; c < 4; c++) {
                float b = (c == 0) ? bv.x : (c == 1) ? bv.y : (c == 2) ? bv.z : bv.w;
                h[0][c] = fmaf(a0, b, h[0][c]);
                h[1][c] = fmaf(a1, b, h[1][c]);
            }
        }
#pragma unroll
        for (int r = 0; r < 2; r++) {
            if (r0 + r < nvalid) {
#pragma unroll
                for (int c = 0; c < 4; c++)
                    out[(size_t)(nb + r0 + r) * 32 + c0 + c] = fmaxf(h[r][c], 0.f);
            }
        }
    }
}

// ---------------------------------------------------------------------------
// Launch. Inputs: node_x, edge_x, z_init, W_pre, b_pre, W_upd, b_upd, src, dst
// ---------------------------------------------------------------------------
extern "C" void kernel_launch(void* const* d_in, const int* in_sizes, int n_in,
                              void* d_out, int out_size) {
    const float* node_x = (const float*)d_in[0];
    const float* edge_x = (const float*)d_in[1];
    const float* z_init = (const float*)d_in[2];
    const float* W_pre  = (const float*)d_in[3];
    const float* b_pre  = (const float*)d_in[4];
    const float* W_upd  = (const float*)d_in[5];
    const float* b_upd  = (const float*)d_in[6];
    const int*   src    = (const int*)d_in[7];
    const int*   dst    = (const int*)d_in[8];
    float* out = (float*)d_out;

    int n_nodes = in_sizes[0] / 32;   // 100000
    int n_edges = in_sizes[7];        // 1600000
    int nb = (n_nodes + SCAN_T - 1) / SCAN_T;   // 98

    mp_zero_kernel<<<(n_nodes + 255) / 256, 256>>>(n_nodes);
    mp_hist_kernel<<<(n_edges + 255) / 256, 256>>>(dst, n_edges);
    mp_scan1_kernel<<<nb, SCAN_T>>>(n_nodes);
    mp_scan2_kernel<<<1, SCAN_T>>>(nb);
    mp_scan3_kernel<<<nb, SCAN_T>>>(n_nodes);
    mp_permute_kernel<<<(n_edges + 255) / 256, 256>>>(src, dst, n_edges);
    mp_gather_kernel<<<(n_nodes * 32 + 255) / 256, 256>>>(node_x, edge_x, n_nodes);
    mp_epilogue_kernel<<<(n_nodes + 63) / 64, 256>>>(
        node_x, z_init, W_pre, b_pre, W_upd, b_upd, out, n_nodes);
}

// round 11
// speedup vs baseline: 1.9599x; 1.0529x over previous
#include <cuda_runtime.h>

// Problem constants (N=100000, E=1600000, ND=ED=OD=32)
#define NODES_MAX 100000
#define EDGES_MAX 1600000
#define SCAN_T 1024

// Device-global scratch (no allocations allowed).
__device__ int   g_count[NODES_MAX];      // in-degree
__device__ int   g_rowtmp[NODES_MAX];     // block-local exclusive scan
__device__ int   g_row[NODES_MAX];        // CSR row offsets
__device__ int   g_cursor[NODES_MAX];     // permutation cursors
__device__ int   g_part[256];             // scan partials
__device__ int2  g_epair[EDGES_MAX];      // dst-sorted (src, eid)

// ---------------------------------------------------------------------------
// 1. zero histogram
// ---------------------------------------------------------------------------
__global__ void mp_zero_kernel(int n_nodes) {
    int i = blockIdx.x * blockDim.x + threadIdx.x;
    if (i < n_nodes) g_count[i] = 0;
}

// ---------------------------------------------------------------------------
// 2. in-degree histogram
// ---------------------------------------------------------------------------
__global__ void mp_hist_kernel(const int* __restrict__ dst, int n_edges) {
    int e = blockIdx.x * blockDim.x + threadIdx.x;
    if (e < n_edges) atomicAdd(&g_count[__ldg(dst + e)], 1);
}

// ---------------------------------------------------------------------------
// 3a. block exclusive scan (shuffle-based, 2 barriers)
// ---------------------------------------------------------------------------
__global__ void mp_scan1_kernel(int n_nodes) {
    __shared__ int wsum[32];
    int t = threadIdx.x;
    int idx = blockIdx.x * SCAN_T + t;
    int v = (idx < n_nodes) ? g_count[idx] : 0;
    int x = v;
#pragma unroll
    for (int o = 1; o < 32; o <<= 1) {
        int y = __shfl_up_sync(0xffffffffu, x, o);
        if ((t & 31) >= o) x += y;
    }
    if ((t & 31) == 31) wsum[t >> 5] = x;
    __syncthreads();
    if (t < 32) {
        int s = wsum[t];
#pragma unroll
        for (int o = 1; o < 32; o <<= 1) {
            int y = __shfl_up_sync(0xffffffffu, s, o);
            if (t >= o) s += y;
        }
        wsum[t] = s;
    }
    __syncthreads();
    int base = (t >= 32) ? wsum[(t >> 5) - 1] : 0;
    int incl = x + base;
    if (idx < n_nodes) g_rowtmp[idx] = incl - v;   // exclusive
    if (t == SCAN_T - 1) g_part[blockIdx.x] = incl;
}

// 3b. scan of block partials (nb <= 128)
__global__ void mp_scan2_kernel(int nb) {
    __shared__ int wsum[4];
    int t = threadIdx.x;   // 128 threads
    int v = (t < nb) ? g_part[t] : 0;
    int x = v;
#pragma unroll
    for (int o = 1; o < 32; o <<= 1) {
        int y = __shfl_up_sync(0xffffffffu, x, o);
        if ((t & 31) >= o) x += y;
    }
    if ((t & 31) == 31) wsum[t >> 5] = x;
    __syncthreads();
    if (t == 0) {
        wsum[1] += wsum[0];
        wsum[2] += wsum[1];
        wsum[3] += wsum[2];
    }
    __syncthreads();
    int base = (t >= 32) ? wsum[(t >> 5) - 1] : 0;
    if (t < nb) g_part[t] = x + base - v;          // exclusive
}

// 3c. combine -> g_row, init cursors
__global__ void mp_scan3_kernel(int n_nodes) {
    int idx = blockIdx.x * blockDim.x + threadIdx.x;
    if (idx < n_nodes) {
        int r = g_rowtmp[idx] + g_part[idx / SCAN_T];
        g_row[idx] = r;
        g_cursor[idx] = r;
    }
}

// ---------------------------------------------------------------------------
// 4. permutation: (src, eid) into dst-sorted order (int atomics only)
// ---------------------------------------------------------------------------
__global__ void mp_permute_kernel(const int* __restrict__ src,
                                  const int* __restrict__ dst,
                                  int n_edges) {
    int e = blockIdx.x * blockDim.x + threadIdx.x;
    if (e >= n_edges) return;
    int d = __ldg(dst + e);
    int pos = atomicAdd(&g_cursor[d], 1);
    g_epair[pos] = make_int2(__ldg(src + e), e);
}

// ---------------------------------------------------------------------------
// 5. FUSED gather + epilogue. Block = 256 threads = 64 nodes.
//    Phase 1: 8 warps x 8 nodes: CSR walk, lane=(edge_sub, f4-chunk),
//             float4 loads, no inner-loop shuffles, results -> smem sA.
//    Phase 2: Z = relu(S@W_pre + deg*b_pre) (deg==0 -> z_init)
//             H = relu([X|Z]@W_upd + b_upd)   (register-blocked GEMMs)
// ---------------------------------------------------------------------------
__global__ void __launch_bounds__(256)
mp_fused_kernel(const float4* __restrict__ node_x4,
                const float4* __restrict__ edge_x4,
                const float* __restrict__ node_x,
                const float* __restrict__ z_init,
                const float* __restrict__ W_pre,   // [64,64]
                const float* __restrict__ b_pre,   // [64]
                const float* __restrict__ W_upd,   // [96,32]
                const float* __restrict__ b_upd,   // [32]
                float* __restrict__ out,           // [N,32]
                int n_nodes) {
    __shared__ float sA[64 * 65];     // S tile, later Z tile (pitch 65)
    __shared__ float sW[64 * 64];     // W_pre, later W_upd
    __shared__ float sX[64 * 33];     // node_x tile
    __shared__ float sbp[64];
    __shared__ float sbu[32];
    __shared__ float sdeg[64];

    int t = threadIdx.x;
    int nb0 = blockIdx.x * 64;
    int nvalid = n_nodes - nb0;
    if (nvalid > 64) nvalid = 64;

    // ---- stage weights / X / biases / deg ----
    for (int idx = t; idx < 64 * 64; idx += 256) sW[idx] = W_pre[idx];
    for (int idx = t; idx < 64 * 32; idx += 256) {
        int r = idx >> 5, c = idx & 31;
        sX[r * 33 + c] = (r < nvalid) ? node_x[(size_t)(nb0 + r) * 32 + c] : 0.f;
    }
    if (t < 64) {
        sbp[t]  = b_pre[t];
        sdeg[t] = (t < nvalid) ? (float)g_count[nb0 + t] : 0.f;
    }
    if (t < 32) sbu[t] = b_upd[t];

    // ---- phase 1: gather. warp w handles local nodes w*8 .. w*8+7 ----
    {
        int w = t >> 5, lane = t & 31;
        int sub = lane >> 3;          // edge within 4-group
        int f4  = lane & 7;           // float4 chunk of the 32-float row
        for (int i = 0; i < 8; i++) {
            int ln = w * 8 + i;
            float4 s0 = make_float4(0.f, 0.f, 0.f, 0.f);
            float4 s1 = make_float4(0.f, 0.f, 0.f, 0.f);
            if (ln < nvalid) {                       // warp-uniform
                int n = nb0 + ln;
                int start = g_row[n];
                int end   = start + g_count[n];
                for (int base = start; base < end; base += 8) {
                    int i0 = base + sub;
                    int i1 = i0 + 4;
                    if (i0 < end) {
                        int2 p = g_epair[i0];
                        float4 nv = __ldg(node_x4 + (size_t)p.x * 8 + f4);
                        float4 ev = __ldg(edge_x4 + (size_t)p.y * 8 + f4);
                        s0.x += nv.x; s0.y += nv.y; s0.z += nv.z; s0.w += nv.w;
                        s1.x += ev.x; s1.y += ev.y; s1.z += ev.z; s1.w += ev.w;
                    }
                    if (i1 < end) {
                        int2 p = g_epair[i1];
                        float4 nv = __ldg(node_x4 + (size_t)p.x * 8 + f4);
                        float4 ev = __ldg(edge_x4 + (size_t)p.y * 8 + f4);
                        s0.x += nv.x; s0.y += nv.y; s0.z += nv.z; s0.w += nv.w;
                        s1.x += ev.x; s1.y += ev.y; s1.z += ev.z; s1.w += ev.w;
                    }
                }
            }
            // reduce over sub (lane bits 3,4)
#pragma unroll
            for (int off = 8; off <= 16; off <<= 1) {
                s0.x += __shfl_xor_sync(0xffffffffu, s0.x, off);
                s0.y += __shfl_xor_sync(0xffffffffu, s0.y, off);
                s0.z += __shfl_xor_sync(0xffffffffu, s0.z, off);
                s0.w += __shfl_xor_sync(0xffffffffu, s0.w, off);
                s1.x += __shfl_xor_sync(0xffffffffu, s1.x, off);
                s1.y += __shfl_xor_sync(0xffffffffu, s1.y, off);
                s1.z += __shfl_xor_sync(0xffffffffu, s1.z, off);
                s1.w += __shfl_xor_sync(0xffffffffu, s1.w, off);
            }
            if (sub == 0) {
                float* d = &sA[ln * 65 + f4 * 4];
                d[0] = s0.x; d[1] = s0.y; d[2] = s0.z; d[3] = s0.w;
            } else if (sub == 1) {
                float* d = &sA[ln * 65 + 32 + f4 * 4];
                d[0] = s1.x; d[1] = s1.y; d[2] = s1.z; d[3] = s1.w;
            }
        }
    }
    __syncthreads();

    // ---- GEMM1: 64x64, 4x4 micro-tile per thread ----
    float acc[4][4];
    {
        int tx = t & 15, ty = t >> 4;
        int c0 = tx * 4, r0 = ty * 4;
#pragma unroll
        for (int r = 0; r < 4; r++)
#pragma unroll
            for (int c = 0; c < 4; c++) acc[r][c] = sdeg[r0 + r] * sbp[c0 + c];

#pragma unroll 8
        for (int k = 0; k < 64; k++) {
            float a0 = sA[(r0 + 0) * 65 + k];
            float a1 = sA[(r0 + 1) * 65 + k];
            float a2 = sA[(r0 + 2) * 65 + k];
            float a3 = sA[(r0 + 3) * 65 + k];
            float4 bv = *(const float4*)&sW[k * 64 + c0];
#pragma unroll
            for (int c = 0; c < 4; c++) {
                float b = (c == 0) ? bv.x : (c == 1) ? bv.y : (c == 2) ? bv.z : bv.w;
                acc[0][c] = fmaf(a0, b, acc[0][c]);
                acc[1][c] = fmaf(a1, b, acc[1][c]);
                acc[2][c] = fmaf(a2, b, acc[2][c]);
                acc[3][c] = fmaf(a3, b, acc[3][c]);
            }
        }
    }
    __syncthreads();     // all reads of sA (S) and sW (W_pre) done

    // ---- write Z into sA; reload sW with W_upd ----
    {
        int tx = t & 15, ty = t >> 4;
        int c0 = tx * 4, r0 = ty * 4;
#pragma unroll
        for (int r = 0; r < 4; r++)
#pragma unroll
            for (int c = 0; c < 4; c++)
                sA[(r0 + r) * 65 + c0 + c] = fmaxf(acc[r][c], 0.f);
    }
    for (int idx = t; idx < 96 * 32; idx += 256) sW[idx] = W_upd[idx];
    __syncthreads();

    // ---- deg==0 rows take z_init (rare) ----
    if (t < nvalid && sdeg[t] == 0.f) {
        for (int c = 0; c < 64; c++)
            sA[t * 65 + c] = z_init[(size_t)(nb0 + t) * 64 + c];
    }
    __syncthreads();

    // ---- GEMM2: 64x32, 2x4 micro-tile per thread ----
    {
        int tx = t & 7, ty = t >> 3;
        int c0 = tx * 4, r0 = ty * 2;
        float h[2][4];
#pragma unroll
        for (int r = 0; r < 2; r++)
#pragma unroll
            for (int c = 0; c < 4; c++) h[r][c] = sbu[c0 + c];

#pragma unroll 8
        for (int k = 0; k < 32; k++) {       // node_x part (rows 0..31)
            float a0 = sX[(r0 + 0) * 33 + k];
            float a1 = sX[(r0 + 1) * 33 + k];
            float4 bv = *(const float4*)&sW[k * 32 + c0];
#pragma unroll
            for (int c = 0; c < 4; c++) {
                float b = (c == 0) ? bv.x : (c == 1) ? bv.y : (c == 2) ? bv.z : bv.w;
                h[0][c] = fmaf(a0, b, h[0][c]);
                h[1][c] = fmaf(a1, b, h[1][c]);
            }
        }
#pragma unroll 8
        for (int k = 0; k < 64; k++) {       // z part (rows 32..95)
            float a0 = sA[(r0 + 0) * 65 + k];
            float a1 = sA[(r0 + 1) * 65 + k];
            float4 bv = *(const float4*)&sW[(32 + k) * 32 + c0];
#pragma unroll
            for (int c = 0; c < 4; c++) {
                float b = (c == 0) ? bv.x : (c == 1) ? bv.y : (c == 2) ? bv.z : bv.w;
                h[0][c] = fmaf(a0, b, h[0][c]);
                h[1][c] = fmaf(a1, b, h[1][c]);
            }
        }
#pragma unroll
        for (int r = 0; r < 2; r++) {
            if (r0 + r < nvalid) {
#pragma unroll
                for (int c = 0; c < 4; c++)
                    out[(size_t)(nb0 + r0 + r) * 32 + c0 + c] = fmaxf(h[r][c], 0.f);
            }
        }
    }
}

// ---------------------------------------------------------------------------
// Launch. Inputs: node_x, edge_x, z_init, W_pre, b_pre, W_upd, b_upd, src, dst
// ---------------------------------------------------------------------------
extern "C" void kernel_launch(void* const* d_in, const int* in_sizes, int n_in,
                              void* d_out, int out_size) {
    const float* node_x = (const float*)d_in[0];
    const float* edge_x = (const float*)d_in[1];
    const float* z_init = (const float*)d_in[2];
    const float* W_pre  = (const float*)d_in[3];
    const float* b_pre  = (const float*)d_in[4];
    const float* W_upd  = (const float*)d_in[5];
    const float* b_upd  = (const float*)d_in[6];
    const int*   src    = (const int*)d_in[7];
    const int*   dst    = (const int*)d_in[8];
    float* out = (float*)d_out;

    int n_nodes = in_sizes[0] / 32;   // 100000
    int n_edges = in_sizes[7];        // 1600000
    int nb = (n_nodes + SCAN_T - 1) / SCAN_T;   // 98

    mp_zero_kernel<<<(n_nodes + 255) / 256, 256>>>(n_nodes);
    mp_hist_kernel<<<(n_edges + 255) / 256, 256>>>(dst, n_edges);
    mp_scan1_kernel<<<nb, SCAN_T>>>(n_nodes);
    mp_scan2_kernel<<<1, 128>>>(nb);
    mp_scan3_kernel<<<nb, SCAN_T>>>(n_nodes);
    mp_permute_kernel<<<(n_edges + 255) / 256, 256>>>(src, dst, n_edges);
    mp_fused_kernel<<<(n_nodes + 63) / 64, 256>>>(
        (const float4*)node_x, (const float4*)edge_x,
        node_x, z_init, W_pre, b_pre, W_upd, b_upd, out, n_nodes);
}

// round 13
// speedup vs baseline: 1.9948x; 1.0178x over previous
#include <cuda_runtime.h>

// Problem constants (N=100000, E=1600000, ND=ED=OD=32)
#define NODES_MAX 100000
#define EDGES_MAX 1600000
#define SCAN_T 1024

// Device-global scratch (no allocations allowed).
__device__ int   g_count[NODES_MAX];      // in-degree
__device__ int   g_row[NODES_MAX];        // CSR row offsets
__device__ int   g_cursor[NODES_MAX];     // permutation cursors
__device__ int   g_agg[128];              // scan aggregates (+1 = ready flag)
__device__ int2  g_epair[EDGES_MAX];      // dst-sorted (src, eid)

// ---------------------------------------------------------------------------
// 1. zero histogram + scan flags
// ---------------------------------------------------------------------------
__global__ void mp_zero_kernel(int n_nodes) {
    int i = blockIdx.x * blockDim.x + threadIdx.x;
    if (i < n_nodes) g_count[i] = 0;
    if (i < 128) g_agg[i] = 0;
}

// ---------------------------------------------------------------------------
// 2. in-degree histogram
// ---------------------------------------------------------------------------
__global__ void mp_hist_kernel(const int* __restrict__ dst, int n_edges) {
    int e = blockIdx.x * blockDim.x + threadIdx.x;
    if (e < n_edges) atomicAdd(&g_count[__ldg(dst + e)], 1);
}

// ---------------------------------------------------------------------------
// 3. single-kernel exclusive scan (98 blocks, all co-resident on 148 SMs).
//    Each block scans its 1024 counts, publishes aggregate+1 via atomicExch,
//    then polls all predecessors' aggregates and sums them. Deterministic.
// ---------------------------------------------------------------------------
__global__ void __launch_bounds__(SCAN_T)
mp_scan_kernel(int n_nodes) {
    __shared__ int wsum[32];
    __shared__ int sbase;
    int t = threadIdx.x, b = blockIdx.x;
    int idx = b * SCAN_T + t;
    int v = (idx < n_nodes) ? g_count[idx] : 0;

    // warp inclusive scan
    int x = v;
#pragma unroll
    for (int o = 1; o < 32; o <<= 1) {
        int y = __shfl_up_sync(0xffffffffu, x, o);
        if ((t & 31) >= o) x += y;
    }
    if ((t & 31) == 31) wsum[t >> 5] = x;
    __syncthreads();
    if (t < 32) {
        int s = wsum[t];
#pragma unroll
        for (int o = 1; o < 32; o <<= 1) {
            int y = __shfl_up_sync(0xffffffffu, s, o);
            if (t >= o) s += y;
        }
        wsum[t] = s;
    }
    __syncthreads();
    int incl = x + ((t >= 32) ? wsum[(t >> 5) - 1] : 0);
    int total = wsum[31];

    if (t == 0) {
        sbase = 0;
        atomicExch(&g_agg[b], total + 1);   // publish: value+1 doubles as flag
    }
    __syncthreads();                         // sbase=0 visible

    if (t < b) {                             // b <= 97 predecessors
        int w;
        do { w = atomicAdd(&g_agg[t], 0); } while (w == 0);
        atomicAdd(&sbase, w - 1);
    }
    __syncthreads();

    if (idx < n_nodes) {
        int r = sbase + incl - v;            // exclusive prefix
        g_row[idx] = r;
        g_cursor[idx] = r;
    }
}

// ---------------------------------------------------------------------------
// 4. permutation: (src, eid) into dst-sorted order (int atomics only)
// ---------------------------------------------------------------------------
__global__ void mp_permute_kernel(const int* __restrict__ src,
                                  const int* __restrict__ dst,
                                  int n_edges) {
    int e = blockIdx.x * blockDim.x + threadIdx.x;
    if (e >= n_edges) return;
    int d = __ldg(dst + e);
    int pos = atomicAdd(&g_cursor[d], 1);
    g_epair[pos] = make_int2(__ldg(src + e), e);
}

// ---------------------------------------------------------------------------
// 5. FUSED gather + epilogue. Block = 256 threads = 32 nodes (4 per warp).
//    Phase 1: gather with lane=(edge_sub, f4-chunk), float4 loads -> sA.
//    Phase 2: Z = relu(S@W_pre + deg*b_pre) (deg==0 -> z_init)
//             H = relu([X|Z]@W_upd + b_upd)
// ---------------------------------------------------------------------------
__global__ void __launch_bounds__(256, 5)
mp_fused_kernel(const float4* __restrict__ node_x4,
                const float4* __restrict__ edge_x4,
                const float* __restrict__ node_x,
                const float* __restrict__ z_init,
                const float* __restrict__ W_pre,   // [64,64]
                const float* __restrict__ b_pre,   // [64]
                const float* __restrict__ W_upd,   // [96,32]
                const float* __restrict__ b_upd,   // [32]
                float* __restrict__ out,           // [N,32]
                int n_nodes) {
    __shared__ float sA[32 * 65];     // S tile, later Z tile (pitch 65)
    __shared__ float sW[64 * 64];     // W_pre, later W_upd (96*32 fits)
    __shared__ float sX[32 * 33];     // node_x tile
    __shared__ float sbp[64];
    __shared__ float sbu[32];
    __shared__ float sdeg[32];        // degree as float (GEMM1 bias)
    __shared__ int   srow[32];        // CSR start
    __shared__ int   scnt[32];        // degree as int (gather)

    int t = threadIdx.x;
    int nb0 = blockIdx.x * 32;
    int nvalid = n_nodes - nb0;
    if (nvalid > 32) nvalid = 32;

    // ---- stage weights / X / biases / row info ----
    for (int idx = t; idx < 64 * 64; idx += 256) sW[idx] = W_pre[idx];
    for (int idx = t; idx < 32 * 32; idx += 256) {
        int r = idx >> 5, c = idx & 31;
        sX[r * 33 + c] = (r < nvalid) ? node_x[(size_t)(nb0 + r) * 32 + c] : 0.f;
    }
    if (t < 64) sbp[t] = b_pre[t];
    if (t < 32) {
        sbu[t] = b_upd[t];
        int cnt = (t < nvalid) ? g_count[nb0 + t] : 0;
        scnt[t] = cnt;
        sdeg[t] = (float)cnt;
        srow[t] = (t < nvalid) ? g_row[nb0 + t] : 0;
    }
    __syncthreads();

    // ---- phase 1: gather. warp w handles local nodes w*4 .. w*4+3 ----
    {
        int w = t >> 5, lane = t & 31;
        int sub = lane >> 3;          // edge slot within 4-group
        int f4  = lane & 7;           // float4 chunk of the 32-float row
#pragma unroll
        for (int i = 0; i < 4; i++) {
            int ln = w * 4 + i;
            float4 s0 = make_float4(0.f, 0.f, 0.f, 0.f);
            float4 s1 = make_float4(0.f, 0.f, 0.f, 0.f);
            if (ln < nvalid) {                       // warp-uniform
                int start = srow[ln];
                int end   = start + scnt[ln];
                for (int base = start; base < end; base += 8) {
                    int i0 = base + sub;
                    int i1 = i0 + 4;
                    if (i0 < end) {
                        int2 p = g_epair[i0];
                        float4 nv = __ldg(node_x4 + (size_t)p.x * 8 + f4);
                        float4 ev = __ldg(edge_x4 + (size_t)p.y * 8 + f4);
                        s0.x += nv.x; s0.y += nv.y; s0.z += nv.z; s0.w += nv.w;
                        s1.x += ev.x; s1.y += ev.y; s1.z += ev.z; s1.w += ev.w;
                    }
                    if (i1 < end) {
                        int2 p = g_epair[i1];
                        float4 nv = __ldg(node_x4 + (size_t)p.x * 8 + f4);
                        float4 ev = __ldg(edge_x4 + (size_t)p.y * 8 + f4);
                        s0.x += nv.x; s0.y += nv.y; s0.z += nv.z; s0.w += nv.w;
                        s1.x += ev.x; s1.y += ev.y; s1.z += ev.z; s1.w += ev.w;
                    }
                }
            }
            // reduce over sub (lane bits 3,4)
#pragma unroll
            for (int off = 8; off <= 16; off <<= 1) {
                s0.x += __shfl_xor_sync(0xffffffffu, s0.x, off);
                s0.y += __shfl_xor_sync(0xffffffffu, s0.y, off);
                s0.z += __shfl_xor_sync(0xffffffffu, s0.z, off);
                s0.w += __shfl_xor_sync(0xffffffffu, s0.w, off);
                s1.x += __shfl_xor_sync(0xffffffffu, s1.x, off);
                s1.y += __shfl_xor_sync(0xffffffffu, s1.y, off);
                s1.z += __shfl_xor_sync(0xffffffffu, s1.z, off);
                s1.w += __shfl_xor_sync(0xffffffffu, s1.w, off);
            }
            if (sub == 0) {
                float* d = &sA[ln * 65 + f4 * 4];
                d[0] = s0.x; d[1] = s0.y; d[2] = s0.z; d[3] = s0.w;
            } else if (sub == 1) {
                float* d = &sA[ln * 65 + 32 + f4 * 4];
                d[0] = s1.x; d[1] = s1.y; d[2] = s1.z; d[3] = s1.w;
            }
        }
    }
    __syncthreads();

    // ---- GEMM1: 32x64 output, 2x4 micro-tile per thread ----
    float acc[2][4];
    {
        int tx = t & 15, ty = t >> 4;     // tx: col group, ty: 0..15 row pair
        int c0 = tx * 4, r0 = ty * 2;
#pragma unroll
        for (int r = 0; r < 2; r++)
#pragma unroll
            for (int c = 0; c < 4; c++) acc[r][c] = sdeg[r0 + r] * sbp[c0 + c];

#pragma unroll 8
        for (int k = 0; k < 64; k++) {
            float a0 = sA[(r0 + 0) * 65 + k];
            float a1 = sA[(r0 + 1) * 65 + k];
            float4 bv = *(const float4*)&sW[k * 64 + c0];
#pragma unroll
            for (int c = 0; c < 4; c++) {
                float b = (c == 0) ? bv.x : (c == 1) ? bv.y : (c == 2) ? bv.z : bv.w;
                acc[0][c] = fmaf(a0, b, acc[0][c]);
                acc[1][c] = fmaf(a1, b, acc[1][c]);
            }
        }
    }
    __syncthreads();     // all reads of sA (S) and sW (W_pre) done

    // ---- write Z into sA; reload sW with W_upd ----
    {
        int tx = t & 15, ty = t >> 4;
        int c0 = tx * 4, r0 = ty * 2;
#pragma unroll
        for (int r = 0; r < 2; r++)
#pragma unroll
            for (int c = 0; c < 4; c++)
                sA[(r0 + r) * 65 + c0 + c] = fmaxf(acc[r][c], 0.f);
    }
    for (int idx = t; idx < 96 * 32; idx += 256) sW[idx] = W_upd[idx];
    __syncthreads();

    // ---- deg==0 rows take z_init (rare) ----
    if (t < nvalid && scnt[t] == 0) {
        for (int c = 0; c < 64; c++)
            sA[t * 65 + c] = z_init[(size_t)(nb0 + t) * 64 + c];
    }
    __syncthreads();

    // ---- GEMM2: 32x32 output, 1x4 micro-tile per thread ----
    {
        int tx = t & 7, r0 = t >> 3;      // r0: 0..31
        int c0 = tx * 4;
        float h[4];
#pragma unroll
        for (int c = 0; c < 4; c++) h[c] = sbu[c0 + c];

#pragma unroll 8
        for (int k = 0; k < 32; k++) {       // node_x part (rows 0..31)
            float a = sX[r0 * 33 + k];
            float4 bv = *(const float4*)&sW[k * 32 + c0];
            h[0] = fmaf(a, bv.x, h[0]);
            h[1] = fmaf(a, bv.y, h[1]);
            h[2] = fmaf(a, bv.z, h[2]);
            h[3] = fmaf(a, bv.w, h[3]);
        }
#pragma unroll 8
        for (int k = 0; k < 64; k++) {       // z part (rows 32..95)
            float a = sA[r0 * 65 + k];
            float4 bv = *(const float4*)&sW[(32 + k) * 32 + c0];
            h[0] = fmaf(a, bv.x, h[0]);
            h[1] = fmaf(a, bv.y, h[1]);
            h[2] = fmaf(a, bv.z, h[2]);
            h[3] = fmaf(a, bv.w, h[3]);
        }
        if (r0 < nvalid) {
#pragma unroll
            for (int c = 0; c < 4; c++)
                out[(size_t)(nb0 + r0) * 32 + c0 + c] = fmaxf(h[c], 0.f);
        }
    }
}

// ---------------------------------------------------------------------------
// Launch. Inputs: node_x, edge_x, z_init, W_pre, b_pre, W_upd, b_upd, src, dst
// ---------------------------------------------------------------------------
extern "C" void kernel_launch(void* const* d_in, const int* in_sizes, int n_in,
                              void* d_out, int out_size) {
    const float* node_x = (const float*)d_in[0];
    const float* edge_x = (const float*)d_in[1];
    const float* z_init = (const float*)d_in[2];
    const float* W_pre  = (const float*)d_in[3];
    const float* b_pre  = (const float*)d_in[4];
    const float* W_upd  = (const float*)d_in[5];
    const float* b_upd  = (const float*)d_in[6];
    const int*   src    = (const int*)d_in[7];
    const int*   dst    = (const int*)d_in[8];
    float* out = (float*)d_out;

    int n_nodes = in_sizes[0] / 32;   // 100000
    int n_edges = in_sizes[7];        // 1600000
    int nb = (n_nodes + SCAN_T - 1) / SCAN_T;   // 98 (all co-resident)

    mp_zero_kernel<<<(n_nodes + 255) / 256, 256>>>(n_nodes);
    mp_hist_kernel<<<(n_edges + 255) / 256, 256>>>(dst, n_edges);
    mp_scan_kernel<<<nb, SCAN_T>>>(n_nodes);
    mp_permute_kernel<<<(n_edges + 255) / 256, 256>>>(src, dst, n_edges);
    mp_fused_kernel<<<(n_nodes + 31) / 32, 256>>>(
        (const float4*)node_x, (const float4*)edge_x,
        node_x, z_init, W_pre, b_pre, W_upd, b_upd, out, n_nodes);
}